// round 15
// baseline (speedup 1.0000x reference)
#include <cuda_runtime.h>
#include <cuda_fp16.h>
#include <math.h>

#define NB   256
#define HDIM 2048
#define QKVD 8192
#define QSZ  4096
#define TGT  4096
#define NC   32

// ---------------- scratch (no allocations allowed) ----------------
__device__ float g_core_base[NB * TGT];     // raw qkv-tail gemm output
__device__ float g_gate[NB * TGT];          // sigmoid(hidden @ Wgate^T)
__device__ float g_ab[NB * 64];             // [a(32) | b(32)] per batch
__device__ float g_core[NB * TGT];          // normalized gated core

__device__ __forceinline__ float sigmoidf_(float x) { return 1.0f / (1.0f + expf(-x)); }

// ---------------- mma.sync fp16 plumbing ----------------
__device__ __forceinline__ void ldsm4(unsigned* r, unsigned addr) {
    asm volatile("ldmatrix.sync.aligned.m8n8.x4.shared.b16 {%0,%1,%2,%3}, [%4];"
                 : "=r"(r[0]), "=r"(r[1]), "=r"(r[2]), "=r"(r[3]) : "r"(addr));
}
#define MMA16816(d, a, b) asm volatile( \
    "mma.sync.aligned.m16n8k16.row.col.f32.f16.f16.f32 " \
    "{%0,%1,%2,%3}, {%4,%5,%6,%7}, {%8,%9}, {%0,%1,%2,%3};" \
    : "+f"((d)[0]), "+f"((d)[1]), "+f"((d)[2]), "+f"((d)[3]) \
    : "r"((a)[0]), "r"((a)[1]), "r"((a)[2]), "r"((a)[3]), "r"((b)[0]), "r"((b)[1]))

// split x into fp16 hi + fp16 lo (pairs packed into u32, low element first)
__device__ __forceinline__ void cvt2(float a, float b, unsigned& hi, unsigned& lo) {
    __half2 h = __floats2half2_rn(a, b);
    float ra = a - __low2float(h);
    float rb = b - __high2float(h);
    __half2 l = __floats2half2_rn(ra, rb);
    hi = *(unsigned*)&h;
    lo = *(unsigned*)&l;
}

// ---------------- mbarrier plumbing ----------------
__device__ __forceinline__ unsigned smem_u32(const void* p) {
    unsigned a;
    asm("{ .reg .u64 t; cvta.to.shared.u64 t, %1; cvt.u32.u64 %0, t; }" : "=r"(a) : "l"(p));
    return a;
}
__device__ __forceinline__ void mbar_init(unsigned a, unsigned c) {
    asm volatile("mbarrier.init.shared.b64 [%0], %1;" :: "r"(a), "r"(c) : "memory");
}
__device__ __forceinline__ void mbar_arrive(unsigned a) {
    asm volatile("mbarrier.arrive.shared.b64 _, [%0];" :: "r"(a) : "memory");
}
__device__ __forceinline__ void mbar_wait(unsigned a, unsigned p) {
    asm volatile("{\n\t.reg .pred P;\nW%=:\n\t"
                 "mbarrier.try_wait.parity.acquire.cta.shared::cta.b64 P, [%0], %1, 0x989680;\n\t"
                 "@!P bra W%=;\n\t}" :: "r"(a), "r"(p) : "memory");
}

// smem geometry: stage = BK=32 K-slice of A(128 rows) + B(128 rows), hi/lo planes.
// ROWSTR pad 32->40 halves kills LDSM bank conflicts. 3-stage ring.
#define ROWSTR 40
#define PLH    (128 * ROWSTR)         // 5120 halves per plane
#define STGH   (4 * PLH)              // 20480 halves per stage (AH,AL,BH,BL)
#define OFF_AH 0
#define OFF_AL PLH
#define OFF_BH (2 * PLH)
#define OFF_BL (3 * PLH)
#define NSTAGE 3
#define SMEM_BYTES (128 + NSTAGE * STGH * 2)   // 123008 B

// mbarriers at smem[0..47]: full[s] = +s*16, empty[s] = +s*16+8
// =====================================================================
// Warp-specialized GEMM engine: 384 threads.
//   warps 0-7  : consumers (2x4 grid, warp tile 64x32) — LDSM + MMA only
//   warps 8-11 : producers — LDG fp32 -> hi/lo cvt -> STS only
// 2-pass (A_hi*B_hi + A_hi*B_lo); 3-pass adds A_lo*B_hi when three=true.
// =====================================================================
__device__ __forceinline__ void gemm_ws(
    const float* const* pA, const float* const* pB, const int* soff,
    int NT, bool three, unsigned mbase, __half* hdata,
    float (*acc)[4][4], int tid)
{
    const int wid = tid >> 5, lane = tid & 31;
    if (wid >= 8) {
        // ---------------- producer ----------------
        for (int t = 0; t < NT; ++t) {
            int s = t % NSTAGE;
            unsigned ph = ((unsigned)(t / NSTAGE) & 1u) ^ 1u;
            float4 ra[8], rb[8];
#pragma unroll
            for (int i = 0; i < 8; ++i) {
                ra[i] = *(const float4*)(pA[i] + t * 32);
                rb[i] = *(const float4*)(pB[i] + t * 32);
            }
            mbar_wait(mbase + s * 16 + 8, ph);          // empty[s]
            __half* dst = hdata + s * STGH;
#pragma unroll
            for (int i = 0; i < 8; ++i) {
                unsigned h0, l0, h1, l1;
                cvt2(ra[i].x, ra[i].y, h0, l0); cvt2(ra[i].z, ra[i].w, h1, l1);
                *(uint2*)(dst + OFF_AH + soff[i]) = make_uint2(h0, h1);
                if (three) *(uint2*)(dst + OFF_AL + soff[i]) = make_uint2(l0, l1);
                cvt2(rb[i].x, rb[i].y, h0, l0); cvt2(rb[i].z, rb[i].w, h1, l1);
                *(uint2*)(dst + OFF_BH + soff[i]) = make_uint2(h0, h1);
                *(uint2*)(dst + OFF_BL + soff[i]) = make_uint2(l0, l1);
            }
            mbar_arrive(mbase + s * 16);                // full[s]
        }
    } else {
        // ---------------- consumer ----------------
        const int wm = wid >> 2, wn = wid & 3;
        const int arow = wm * 64 + (lane & 15);
        const int akk  = (lane >> 4) << 3;
        const int brow = wn * 32 + ((lane >> 4) << 3) + (lane & 7);
        const int bkk  = ((lane >> 3) & 1) << 3;
        const unsigned dbase = smem_u32(hdata);
        for (int t = 0; t < NT; ++t) {
            int s = t % NSTAGE;
            unsigned ph = (unsigned)(t / NSTAGE) & 1u;
            mbar_wait(mbase + s * 16, ph);              // full[s]
            const unsigned pb = dbase + (unsigned)(s * STGH * 2);
#pragma unroll
            for (int ks = 0; ks < 2; ++ks) {
                const int koff = ks * 16;
                unsigned ah[4][4], al[4][4], bh[2][4], bl[2][4];
#pragma unroll
                for (int mf = 0; mf < 4; ++mf) {
                    unsigned aoff = (unsigned)(((arow + mf * 16) * ROWSTR + akk + koff) * 2);
                    ldsm4(ah[mf], pb + OFF_AH * 2 + aoff);
                    if (three) ldsm4(al[mf], pb + OFF_AL * 2 + aoff);
                }
#pragma unroll
                for (int pr = 0; pr < 2; ++pr) {
                    unsigned boff = (unsigned)(((brow + pr * 16) * ROWSTR + bkk + koff) * 2);
                    ldsm4(bh[pr], pb + OFF_BH * 2 + boff);
                    ldsm4(bl[pr], pb + OFF_BL * 2 + boff);
                }
#pragma unroll
                for (int mf = 0; mf < 4; ++mf)
#pragma unroll
                    for (int nf = 0; nf < 4; ++nf) {
                        unsigned* bhp = &bh[nf >> 1][(nf & 1) * 2];
                        unsigned* blp = &bl[nf >> 1][(nf & 1) * 2];
                        MMA16816(acc[mf][nf], ah[mf], bhp);
                        MMA16816(acc[mf][nf], ah[mf], blp);
                        if (three) MMA16816(acc[mf][nf], al[mf], bhp);
                    }
            }
            mbar_arrive(mbase + s * 16 + 8);            // empty[s]
        }
    }
}

// =====================================================================
// K1: fused GEMM over N = [qkv tail | gate | alpha/beta], M=256, K=2048.
// BM=128 (grid.y=2), BN=128 (grid.x=65). 1 CTA/SM, warp-specialized.
// =====================================================================
__global__ void __launch_bounds__(384, 1) k_gemm1(
    const float* __restrict__ A,       // hidden [256,2048]
    const float* __restrict__ Wqkv,    // [8192,2048]
    const float* __restrict__ Wgate,   // [4096,2048]
    const float* __restrict__ Walpha,  // [32,2048]
    const float* __restrict__ Wbeta)   // [32,2048]
{
    extern __shared__ char smem[];
    const unsigned mbase = smem_u32(smem);
    __half* hdata = (__half*)(smem + 128);
    const int tid = threadIdx.x;
    if (tid == 0) {
#pragma unroll
        for (int s = 0; s < NSTAGE; ++s) {
            mbar_init(mbase + s * 16, 128);      // full: 128 producer threads
            mbar_init(mbase + s * 16 + 8, 256);  // empty: 256 consumer threads
        }
    }
    __syncthreads();

    const int m0   = blockIdx.y * 128;
    const int nblk = blockIdx.x;
    const int kind = (nblk < 32) ? 0 : (nblk < 64 ? 1 : 2);
    const bool three = (kind == 2);

    const float* pA[8]; const float* pB[8]; int soff[8];
    if (tid >= 256) {
        int ptid = tid - 256;
#pragma unroll
        for (int i = 0; i < 8; ++i) {
            int c = ptid + i * 128;
            int r = c >> 3, kc = c & 7;
            soff[i] = r * ROWSTR + kc * 4;
            pA[i] = A + (size_t)(m0 + r) * HDIM + kc * 4;
            const float* rp;
            if (kind == 0)      rp = Wqkv  + (size_t)(QSZ + nblk * 128 + r) * HDIM;
            else if (kind == 1) rp = Wgate + (size_t)((nblk - 32) * 128 + r) * HDIM;
            else rp = (r < 32) ? Walpha + (size_t)r * HDIM
                     : (r < 64) ? Wbeta + (size_t)(r - 32) * HDIM
                                : Walpha + (size_t)(r & 31) * HDIM;  // dummy rows
            pB[i] = rp + kc * 4;
        }
    }

    float acc[4][4][4];
#pragma unroll
    for (int x = 0; x < 4; ++x)
#pragma unroll
        for (int y = 0; y < 4; ++y)
#pragma unroll
            for (int z = 0; z < 4; ++z) acc[x][y][z] = 0.f;

    gemm_ws(pA, pB, soff, HDIM / 32, three, mbase, hdata, acc, tid);

    if (tid < 256) {
        const int lane = tid & 31, wid = tid >> 5;
        const int wm = wid >> 2, wn = wid & 3;
        const int mb = m0 + wm * 64 + (lane >> 2);
        const int cb = wn * 32 + (lane & 3) * 2;
#pragma unroll
        for (int mf = 0; mf < 4; ++mf)
#pragma unroll
            for (int nf = 0; nf < 4; ++nf)
#pragma unroll
                for (int h = 0; h < 2; ++h) {
                    int m = mb + mf * 16 + h * 8;
                    int col = cb + nf * 8;
                    float v0 = acc[mf][nf][h * 2], v1 = acc[mf][nf][h * 2 + 1];
                    if (kind == 0) {
                        *(float2*)&g_core_base[(size_t)m * TGT + nblk * 128 + col] =
                            make_float2(v0, v1);
                    } else if (kind == 1) {
                        *(float2*)&g_gate[(size_t)m * TGT + (nblk - 32) * 128 + col] =
                            make_float2(sigmoidf_(v0), sigmoidf_(v1));
                    } else if (col < 64) {
                        *(float2*)&g_ab[(size_t)m * 64 + col] = make_float2(v0, v1);
                    }
                }
    }
}

// =====================================================================
// K2: per-batch fused conv + SSM + RMS + gate; zeroes d_out for K3 atomics.
// =====================================================================
__global__ void __launch_bounds__(256) k_fuse(
    const float* __restrict__ bqkv,
    const float* __restrict__ convk,    // [8192,4]
    const float* __restrict__ convst,   // [256,4,8192]
    const float* __restrict__ ssa,
    const float* __restrict__ dtb,
    const float* __restrict__ normw,
    const float* __restrict__ sstate,
    float* __restrict__ out)
{
    __shared__ float s_conv[TGT];
    __shared__ float kg[NC], vg[NC], ssig[NC], red[8];
    __shared__ float s_scale, s_wmean;
    const int b = blockIdx.x, tid = threadIdx.x;
    const int lane = tid & 31, w = tid >> 5;

#pragma unroll
    for (int i = 0; i < 8; ++i) out[(size_t)b * HDIM + tid + i * 256] = 0.f;

#pragma unroll
    for (int i = 0; i < 16; ++i) {
        int idx = tid + i * 256;
        int d = QSZ + idx;
        float val = g_core_base[(size_t)b * TGT + idx] + bqkv[d];
        float4 ck = *(const float4*)(convk + (size_t)d * 4);
        float co = val * ck.w
                 + convst[((size_t)b * 4 + 1) * QKVD + d] * ck.x
                 + convst[((size_t)b * 4 + 2) * QKVD + d] * ck.y
                 + convst[((size_t)b * 4 + 3) * QKVD + d] * ck.z;
        s_conv[idx] = co;
    }
    if (tid == 0) {
        float wm = 0.f;
        for (int i = 0; i < 128; ++i) wm += normw[i];
        s_wmean = wm * (1.0f / 128.0f);
    }
    __syncthreads();

    {
        int gg = tid >> 2, sub = tid & 3;
        const float* p = s_conv + gg * 64 + sub * 16;
        float s = 0.f;
#pragma unroll
        for (int i = 0; i < 16; ++i) s += p[i];
        s += __shfl_xor_sync(0xFFFFFFFFu, s, 1);
        s += __shfl_xor_sync(0xFFFFFFFFu, s, 2);
        if (sub == 0) {
            float mn = s * (1.0f / 64.0f);
            if (gg < NC) kg[gg] = mn; else vg[gg - NC] = mn;
        }
    }
    __syncthreads();

    if (tid < NC) {
        int c = tid;
        float av = g_ab[(size_t)b * 64 + c];
        float bv = g_ab[(size_t)b * 64 + 32 + c];
        float x  = av + dtb[c];
        float sp = (x > 20.f) ? x : log1pf(expf(x));
        float g  = -expf(ssa[c]) * sp;
        float ns = expf(g) * sstate[(size_t)b * NC + c] + sigmoidf_(bv) * vg[c];
        ssig[c]  = ns * sigmoidf_(kg[c]);
    }
    __syncthreads();

    float cv[16]; float sq = 0.f;
#pragma unroll
    for (int i = 0; i < 16; ++i) {
        int idx = tid + i * 256;
        float v = s_conv[idx] + ssig[idx >> 7];
        cv[i] = v; sq += v * v;
    }
#pragma unroll
    for (int o = 16; o; o >>= 1) sq += __shfl_xor_sync(0xFFFFFFFFu, sq, o);
    if (lane == 0) red[w] = sq;
    __syncthreads();
    if (tid == 0) {
        float t = 0.f;
        for (int i = 0; i < 8; ++i) t += red[i];
        s_scale = rsqrtf(t * (1.0f / (float)TGT) + 1e-6f);
    }
    __syncthreads();

    const float scl = s_scale * s_wmean;
#pragma unroll
    for (int i = 0; i < 16; ++i) {
        int idx = tid + i * 256;
        g_core[(size_t)b * TGT + idx] = cv[i] * scl * g_gate[(size_t)b * TGT + idx];
    }
}

// =====================================================================
// K3: out GEMM [256,2048] = g_core[256,4096] @ Wout[2048,4096]^T.
// BM=128, BN=128, split-K=4 (grid.z), warp-specialized 2-pass,
// atomicAdd epilogue straight into d_out.
// =====================================================================
__global__ void __launch_bounds__(384, 1) k_gemm2(const float* __restrict__ Wout,
                                                  float* __restrict__ out)
{
    extern __shared__ char smem[];
    const unsigned mbase = smem_u32(smem);
    __half* hdata = (__half*)(smem + 128);
    const int tid = threadIdx.x;
    if (tid == 0) {
#pragma unroll
        for (int s = 0; s < NSTAGE; ++s) {
            mbar_init(mbase + s * 16, 128);
            mbar_init(mbase + s * 16 + 8, 256);
        }
    }
    __syncthreads();

    const int m0 = blockIdx.y * 128;
    const int n0 = blockIdx.x * 128;
    const int kbeg = blockIdx.z * 1024;

    const float* pA[8]; const float* pB[8]; int soff[8];
    if (tid >= 256) {
        int ptid = tid - 256;
#pragma unroll
        for (int i = 0; i < 8; ++i) {
            int c = ptid + i * 128;
            int r = c >> 3, kc = c & 7;
            soff[i] = r * ROWSTR + kc * 4;
            pA[i] = g_core + (size_t)(m0 + r) * TGT + kbeg + kc * 4;
            pB[i] = Wout   + (size_t)(n0 + r) * TGT + kbeg + kc * 4;
        }
    }

    float acc[4][4][4];
#pragma unroll
    for (int x = 0; x < 4; ++x)
#pragma unroll
        for (int y = 0; y < 4; ++y)
#pragma unroll
            for (int z = 0; z < 4; ++z) acc[x][y][z] = 0.f;

    gemm_ws(pA, pB, soff, 1024 / 32, false, mbase, hdata, acc, tid);

    if (tid < 256) {
        const int lane = tid & 31, wid = tid >> 5;
        const int wm = wid >> 2, wn = wid & 3;
        const int mb = m0 + wm * 64 + (lane >> 2);
        const int cb = n0 + wn * 32 + (lane & 3) * 2;
#pragma unroll
        for (int mf = 0; mf < 4; ++mf)
#pragma unroll
            for (int nf = 0; nf < 4; ++nf)
#pragma unroll
                for (int h = 0; h < 2; ++h) {
                    int m = mb + mf * 16 + h * 8;
                    int col = cb + nf * 8;
                    atomicAdd(&out[(size_t)m * HDIM + col],     acc[mf][nf][h * 2]);
                    atomicAdd(&out[(size_t)m * HDIM + col + 1], acc[mf][nf][h * 2 + 1]);
                }
    }
}

// =====================================================================
extern "C" void kernel_launch(void* const* d_in, const int* in_sizes, int n_in,
                              void* d_out, int out_size)
{
    (void)in_sizes; (void)n_in; (void)out_size;
    const float* hidden = (const float*)d_in[0];
    const float* Wqkv   = (const float*)d_in[1];
    const float* bqkv   = (const float*)d_in[2];
    const float* Wgate  = (const float*)d_in[3];
    const float* Walpha = (const float*)d_in[4];
    const float* Wbeta  = (const float*)d_in[5];
    const float* Wout   = (const float*)d_in[6];
    const float* ssa    = (const float*)d_in[7];
    const float* dtb    = (const float*)d_in[8];
    const float* normw  = (const float*)d_in[9];
    const float* convk  = (const float*)d_in[10];
    const float* sstate = (const float*)d_in[11];
    const float* convst = (const float*)d_in[12];
    float* out = (float*)d_out;

    cudaFuncSetAttribute(k_gemm1, cudaFuncAttributeMaxDynamicSharedMemorySize, SMEM_BYTES);
    cudaFuncSetAttribute(k_gemm2, cudaFuncAttributeMaxDynamicSharedMemorySize, SMEM_BYTES);

    k_gemm1<<<dim3(65, 2), 384, SMEM_BYTES>>>(hidden, Wqkv, Wgate, Walpha, Wbeta);
    k_fuse <<<NB, 256>>>(bqkv, convk, convst, ssa, dtb, normw, sstate, out);
    k_gemm2<<<dim3(16, 2, 4), 384, SMEM_BYTES>>>(Wout, out);
}